// round 13
// baseline (speedup 1.0000x reference)
#include <cuda_runtime.h>
#include <cuda_fp16.h>
#include <mma.h>
#include <cstdint>

using namespace nvcuda;

// ---------------------------------------------------------------------------
// Problem constants
// ---------------------------------------------------------------------------
#define G      8
#define VCODES 512
#define HDIM   128
#define NTOK   16384          // B*T
#define TILE_M 256            // tokens per CTA (8 warps x 32 tokens)
#define TILE_C 64             // codes per chunk
#define NCHUNK 8

#define LDM_H   136           // halves per row (128 + pad), 272 B
#define ROWB    272
#define XPLANE_B (TILE_M * ROWB)      // 69632 B
#define EBUF_B   (TILE_C * ROWB)      // 17408 B (single fp16 plane)

#define SM_X    0
#define SM_E    XPLANE_B                       // 69632: 2 e buffers
#define SM_SC   (SM_E + 2 * EBUF_B)            // 104448: per-warp 16x72 f32
#define SCRATCH_W (16 * 72 * 4)                // 4608 B per warp
#define SM_EN   (SM_SC + 8 * SCRATCH_W)        // 141312: 512 f32 e-norms
#define SM_XN   (SM_EN + 2048)                 // 143360: 256 f32 x-norms
#define SM_TOTAL (SM_XN + 1024)                // 144384 B

// ---------------------------------------------------------------------------
// Device scratch (no allocation allowed)
// ---------------------------------------------------------------------------
__device__ int      g_codes[G * NTOK];
__device__ float    g_enorm[G * VCODES];
__device__ unsigned g_enmax_bits[G];
__device__ __half   g_ehalf[G * VCODES * HDIM];
__device__ int      g_flagcnt;
__device__ int      g_flags[G * NTOK];   // gidx | (full<<31)
__device__ int      g_cand[G * NTOK];    // i1 | (i2<<16)

// ---------------------------------------------------------------------------
#define CP_ASYNC16(SADDR, GPTR) \
    asm volatile("cp.async.cg.shared.global [%0], [%1], 16;" \
        :: "r"(SADDR), "l"(GPTR) : "memory")
#define CP_COMMIT() asm volatile("cp.async.commit_group;" ::: "memory")
#define CP_WAIT1()  asm volatile("cp.async.wait_group 1;" ::: "memory")
#define CP_WAIT0()  asm volatile("cp.async.wait_group 0;" ::: "memory")

// ---------------------------------------------------------------------------
// Prep: e -> fp16 plane; zero flag counter and per-group max norms
// ---------------------------------------------------------------------------
__global__ void pq_prep_kernel(const float* __restrict__ embed) {
    const int i = blockIdx.x * 256 + threadIdx.x;      // 524,288 elems
    g_ehalf[i] = __float2half_rn(embed[i]);
    if (i == 0) g_flagcnt = 0;
    if (i < G) g_enmax_bits[i] = 0u;
}

// ||e||^2 per (g, code), fp32 exact; also per-group max via atomicMax on bits
__global__ void pq_enorm_kernel(const float* __restrict__ embed) {
    const int row  = blockIdx.x * 8 + (threadIdx.x >> 5);
    const int lane = threadIdx.x & 31;
    const float* e = embed + (size_t)row * HDIM;
    const float v0 = e[lane], v1 = e[lane + 32], v2 = e[lane + 64], v3 = e[lane + 96];
    float s = v0 * v0 + v1 * v1 + v2 * v2 + v3 * v3;
    #pragma unroll
    for (int off = 16; off; off >>= 1) s += __shfl_xor_sync(0xffffffffu, s, off);
    if (lane == 0) {
        g_enorm[row] = s;
        atomicMax(&g_enmax_bits[row >> 9], __float_as_uint(s));
    }
}

// ---------------------------------------------------------------------------
// cp.async one e chunk: 64 code-rows x 16 segs of 16B = 1024 segs
// ---------------------------------------------------------------------------
__device__ __forceinline__ void issue_e(uint32_t su, int buf, int g, int cstart,
                                        int tid) {
    const uint32_t sb = su + SM_E + buf * EBUF_B;
    #pragma unroll
    for (int t = 0; t < 4; t++) {
        const int j = t * 256 + tid;                    // 0..1023
        const int r = j >> 4, sgm = j & 15;
        const __half* gp = g_ehalf
            + ((size_t)(g * VCODES + cstart + r)) * HDIM + sgm * 8;
        CP_ASYNC16(sb + r * ROWB + sgm * 16, gp);
    }
}

// ---------------------------------------------------------------------------
// Main kernel: SINGLE fp16 pass WMMA + top-3 tracking + deterministic margin.
// CTA = 256 tokens x 1 group; 8 warps; warp tile = 32 tokens x 64 codes.
// Certain tokens finalize here; ambiguous go to the exact fallback.
// ---------------------------------------------------------------------------
__global__ __launch_bounds__(256, 1) void pq_main_kernel(
    const float* __restrict__ x)
{
    extern __shared__ char smem[];
    const uint32_t su = (uint32_t)__cvta_generic_to_shared(smem);
    const int tid  = threadIdx.x, lane = tid & 31, w = tid >> 5;
    const int g    = blockIdx.y, n0 = blockIdx.x * TILE_M;

    // e-norms -> smem
    *(float*)(smem + SM_EN + tid * 4)         = g_enorm[g * VCODES + tid];
    *(float*)(smem + SM_EN + (tid + 256) * 4) = g_enorm[g * VCODES + 256 + tid];

    issue_e(su, 0, g, 0, tid);
    CP_COMMIT();

    // x prologue: fp32 -> fp16 plane + per-row ||x||^2 (warp covers one row)
    float* xn = reinterpret_cast<float*>(smem + SM_XN);
    #pragma unroll
    for (int t = 0; t < 32; t++) {
        const int j = t * 256 + tid;
        const int r = j >> 5, sg = j & 31;
        const float4 v = *reinterpret_cast<const float4*>(
            x + (size_t)(n0 + r) * (G * HDIM) + g * HDIM + sg * 4);
        __half2* ph = reinterpret_cast<__half2*>(smem + SM_X + r * ROWB + sg * 8);
        ph[0] = __halves2half2(__float2half_rn(v.x), __float2half_rn(v.y));
        ph[1] = __halves2half2(__float2half_rn(v.z), __float2half_rn(v.w));
        float nr = v.x * v.x + v.y * v.y + v.z * v.z + v.w * v.w;
        #pragma unroll
        for (int off = 16; off; off >>= 1)
            nr += __shfl_xor_sync(0xffffffffu, nr, off);
        if (lane == 0) xn[r] = nr;
    }

    // per-(lane,i) top-3 (values; indices for top-2)
    float b1[2], b2[2], b3[2];
    int   i1[2], i2[2];
    #pragma unroll
    for (int i = 0; i < 2; i++) {
        b1[i] = b2[i] = b3[i] = 3.4e38f; i1[i] = 0; i2[i] = 0;
    }

    const float* s_en = reinterpret_cast<const float*>(smem + SM_EN);
    float* sc = reinterpret_cast<float*>(smem + SM_SC + w * SCRATCH_W);
    const int row = lane >> 1, h = lane & 1;

    for (int c = 0; c < NCHUNK; c++) {
        if (c + 1 < NCHUNK) {
            issue_e(su, (c + 1) & 1, g, (c + 1) * TILE_C, tid);
            CP_COMMIT();
            CP_WAIT1();
        } else {
            CP_WAIT0();
        }
        __syncthreads();

        wmma::fragment<wmma::accumulator, 16, 16, 16, float> acc[2][4];
        #pragma unroll
        for (int i = 0; i < 2; i++)
            #pragma unroll
            for (int j = 0; j < 4; j++)
                wmma::fill_fragment(acc[i][j], 0.0f);

        const __half* xp = reinterpret_cast<const __half*>(smem + SM_X);
        const __half* ep = reinterpret_cast<const __half*>(
            smem + SM_E + (c & 1) * EBUF_B);

        #pragma unroll
        for (int ks = 0; ks < 8; ks++) {
            wmma::fragment<wmma::matrix_a, 16, 16, 16, __half,
                           wmma::row_major> A0, A1;
            wmma::load_matrix_sync(A0, xp + (w * 32 + 0)  * LDM_H + ks * 16, LDM_H);
            wmma::load_matrix_sync(A1, xp + (w * 32 + 16) * LDM_H + ks * 16, LDM_H);
            #pragma unroll
            for (int j = 0; j < 4; j++) {
                wmma::fragment<wmma::matrix_b, 16, 16, 16, __half,
                               wmma::col_major> Bf;
                wmma::load_matrix_sync(Bf, ep + j * 16 * LDM_H + ks * 16, LDM_H);
                wmma::mma_sync(acc[0][j], A0, Bf, acc[0][j]);
                wmma::mma_sync(acc[1][j], A1, Bf, acc[1][j]);
            }
        }

        // epilogue: two phases (i = token sub-tile); conflict-free scan
        #pragma unroll
        for (int i = 0; i < 2; i++) {
            #pragma unroll
            for (int j = 0; j < 4; j++)
                wmma::store_matrix_sync(sc + j * 16, acc[i][j], 72,
                                        wmma::mem_row_major);
            __syncwarp();
            #pragma unroll
            for (int t = 0; t < 32; t++) {
                const int cl = h ? (32 + ((t + 1) & 31)) : t;
                const float s = fmaf(-2.f, sc[row * 72 + cl],
                                     s_en[c * TILE_C + cl]);
                const int col = c * TILE_C + cl;
                if (s < b1[i] || (s == b1[i] && col < i1[i])) {
                    b3[i] = b2[i]; b2[i] = b1[i]; i2[i] = i1[i];
                    b1[i] = s; i1[i] = col;
                } else if (s < b2[i] || (s == b2[i] && col < i2[i])) {
                    b3[i] = b2[i]; b2[i] = s; i2[i] = col;
                } else if (s < b3[i]) {
                    b3[i] = s;
                }
            }
            __syncwarp();
        }
        __syncthreads();
    }

    // merge lane pairs (lane ^ 1): top-3 of the union
    const float emax = sqrtf(__uint_as_float(g_enmax_bits[g]));
    #pragma unroll
    for (int i = 0; i < 2; i++) {
        const float ob1 = __shfl_xor_sync(0xffffffffu, b1[i], 1);
        const float ob2 = __shfl_xor_sync(0xffffffffu, b2[i], 1);
        const float ob3 = __shfl_xor_sync(0xffffffffu, b3[i], 1);
        const int   oi1 = __shfl_xor_sync(0xffffffffu, i1[i], 1);
        const int   oi2 = __shfl_xor_sync(0xffffffffu, i2[i], 1);
        if (ob1 < b1[i] || (ob1 == b1[i] && oi1 < i1[i])) {
            if (b1[i] < ob2 || (b1[i] == ob2 && i1[i] < oi2)) {
                b3[i] = fminf(b2[i], ob2);
                b2[i] = b1[i]; i2[i] = i1[i];
            } else {
                b3[i] = fminf(b1[i], ob3);
                b2[i] = ob2; i2[i] = oi2;
            }
            b1[i] = ob1; i1[i] = oi1;
        } else {
            if (ob1 < b2[i] || (ob1 == b2[i] && oi1 < i2[i])) {
                b3[i] = fminf(b2[i], ob2);
                b2[i] = ob1; i2[i] = oi1;
            } else {
                b3[i] = fminf(ob1, b3[i]);
            }
        }
        if (!(lane & 1)) {
            const int tl = w * 32 + i * 16 + row;
            const int gidx = g * NTOK + n0 + tl;
            // deterministic error bound: |approx - exact| <= margin
            const float margin = 0.002f * sqrtf(xn[tl]) * emax + 0.01f;
            const float thr = b1[i] + 2.0f * margin;
            if (!(b2[i] > thr)) {               // ambiguous -> fallback
                const int slot = atomicAdd(&g_flagcnt, 1);
                g_flags[slot] = gidx | ((b3[i] <= thr) ? 0x80000000 : 0);
                g_cand[slot] = (i1[i] & 0xffff) | (i2[i] << 16);
            }
            g_codes[gidx] = i1[i];
        }
    }
}

// ---------------------------------------------------------------------------
// Exact fallback: one warp per ambiguous token.
// mode A (bit31 clear): exact fp32 rescore of the two candidates.
// mode B (bit31 set):   full fp32 rescan of all 512 codes.
// ---------------------------------------------------------------------------
__global__ void pq_fallback_kernel(const float* __restrict__ x,
                                   const float* __restrict__ embed) {
    const int cnt  = g_flagcnt;
    const int lane = threadIdx.x & 31;
    const int wl   = threadIdx.x >> 5;
    const int wg   = blockIdx.x * 8 + wl;
    __shared__ float xs[8][128];
    float* xrow = xs[wl];

    for (int it = wg; it < cnt; it += gridDim.x * 8) {
        const int rec  = g_flags[it];
        const int full = (rec < 0);
        const int gidx = rec & 0x7fffffff;
        const int g = gidx >> 14, n = gidx & (NTOK - 1);
        const float4 xv = reinterpret_cast<const float4*>(
            x + (size_t)n * (G * HDIM) + g * HDIM)[lane];

        if (!full) {
            const int cd = g_cand[it];
            const int c1 = cd & 0xffff, c2 = cd >> 16;
            const float4 a = reinterpret_cast<const float4*>(
                embed + ((size_t)g * VCODES + c1) * HDIM)[lane];
            const float4 b = reinterpret_cast<const float4*>(
                embed + ((size_t)g * VCODES + c2) * HDIM)[lane];
            float d1 = xv.x * a.x + xv.y * a.y + xv.z * a.z + xv.w * a.w;
            float d2 = xv.x * b.x + xv.y * b.y + xv.z * b.z + xv.w * b.w;
            #pragma unroll
            for (int off = 16; off; off >>= 1) {
                d1 += __shfl_xor_sync(0xffffffffu, d1, off);
                d2 += __shfl_xor_sync(0xffffffffu, d2, off);
            }
            if (lane == 0) {
                const float s1 = g_enorm[g * VCODES + c1] - 2.f * d1;
                const float s2 = g_enorm[g * VCODES + c2] - 2.f * d2;
                g_codes[gidx] = (s2 < s1 || (s2 == s1 && c2 < c1)) ? c2 : c1;
            }
        } else {
            reinterpret_cast<float4*>(xrow)[lane] = xv;
            __syncwarp();
            float best = 3.4e38f; int bi = 0;
            for (int c = lane; c < VCODES; c += 32) {
                const float4* er = reinterpret_cast<const float4*>(
                    embed + ((size_t)g * VCODES + c) * HDIM);
                float dot = 0.f;
                #pragma unroll
                for (int q = 0; q < 32; q++) {
                    const float4 e4 = er[q];
                    dot += xrow[4 * q] * e4.x + xrow[4 * q + 1] * e4.y
                         + xrow[4 * q + 2] * e4.z + xrow[4 * q + 3] * e4.w;
                }
                const float s = g_enorm[g * VCODES + c] - 2.f * dot;
                if (s < best) { best = s; bi = c; }   // ascending c: lowest wins
            }
            #pragma unroll
            for (int off = 16; off; off >>= 1) {
                const float ob = __shfl_xor_sync(0xffffffffu, best, off);
                const int   oi = __shfl_xor_sync(0xffffffffu, bi, off);
                if (ob < best || (ob == best && oi < bi)) { best = ob; bi = oi; }
            }
            if (lane == 0) g_codes[gidx] = bi;
            __syncwarp();
        }
    }
}

// ---------------------------------------------------------------------------
// Gather quantized output + codes output (fused).
// ---------------------------------------------------------------------------
__global__ void pq_gather_kernel(const float* __restrict__ embed,
                                 float4* __restrict__ outq,
                                 float* __restrict__ outc) {
    const int i  = blockIdx.x * blockDim.x + threadIdx.x;  // 4,194,304 float4s
    const int h4 = i & 31;
    const int gg = (i >> 5) & 7;
    const int n  = i >> 8;
    const int c  = g_codes[gg * NTOK + n];
    outq[i] = reinterpret_cast<const float4*>(embed)[((gg << 9) + c) * 32 + h4];
    if (h4 == 0) outc[n * 8 + gg] = (float)c;
}

// ---------------------------------------------------------------------------
extern "C" void kernel_launch(void* const* d_in, const int* in_sizes, int n_in,
                              void* d_out, int out_size) {
    const float* x     = (const float*)d_in[0];
    const float* embed = (const float*)d_in[1];
    float* out = (float*)d_out;

    cudaFuncSetAttribute(pq_main_kernel,
                         cudaFuncAttributeMaxDynamicSharedMemorySize, SM_TOTAL);

    pq_prep_kernel<<<(G * VCODES * HDIM) / 256, 256>>>(embed);
    pq_enorm_kernel<<<512, 256>>>(embed);
    pq_main_kernel<<<dim3(NTOK / TILE_M, G), 256, SM_TOTAL>>>(x);
    pq_fallback_kernel<<<256, 256>>>(x, embed);
    pq_gather_kernel<<<(NTOK * G * HDIM / 4) / 256, 256>>>(
        embed, (float4*)out, out + (size_t)NTOK * G * HDIM);
}